// round 1
// baseline (speedup 1.0000x reference)
#include <cuda_runtime.h>
#include <math.h>

#define N_    512
#define CS_   384
#define H_    8
#define C_    128
#define PQ_   8
#define PV_   8
#define KF_   160   // 128 (q/k) + 24 (pts) padded to 160
#define VC_   264   // 128 (v) + 128 (vg_glob) + 4 (qn) + 3 (tr) + 1 pad
#define SEG_  312   // per-head feat segment: 32 + 128 + 8 + 128 + 16
#define FEAT_ 2496  // H_ * SEG_

// ---------------- scratch (static device globals; no allocation) ----------------
static __device__ float g_q[N_*H_*C_];            // [n][h*C+c]
static __device__ float g_kv[N_*H_*2*C_];         // [n][h*256+c]
static __device__ float g_qpl[N_*192];
static __device__ float g_kpl[N_*192];
static __device__ float g_vgl[N_*128];
static __device__ float g_Qf[(size_t)H_*N_*KF_];  // scaled q-features
static __device__ float g_Kf[(size_t)H_*N_*KF_];
static __device__ float g_rowc[H_*N_];
static __device__ float g_colc[H_*N_];
static __device__ float g_qn[N_*4];
static __device__ float g_tr[N_*3];
static __device__ float g_hw[H_];
static __device__ float g_pairb[(size_t)N_*N_*H_];   // z @ W_b
static __device__ float g_zdz[(size_t)N_*N_*32];     // z @ W_dz + b_dz
static __device__ float g_A[(size_t)H_*N_*N_];       // logits -> probs
static __device__ float g_Vcat[(size_t)H_*N_*VC_];
static __device__ float g_Ocat[(size_t)H_*N_*VC_];
static __device__ float g_feats[(size_t)N_*FEAT_];

// ---------------- helpers ----------------
__device__ __forceinline__ void qrot(const float* q, const float* v, float* o) {
    float w=q[0], x=q[1], y=q[2], z=q[3];
    float uvx = y*v[2]-z*v[1];
    float uvy = z*v[0]-x*v[2];
    float uvz = x*v[1]-y*v[0];
    float uuvx = y*uvz-z*uvy;
    float uuvy = z*uvx-x*uvz;
    float uuvz = x*uvy-y*uvx;
    o[0]=v[0]+2.f*(w*uvx+uuvx);
    o[1]=v[1]+2.f*(w*uvy+uuvy);
    o[2]=v[2]+2.f*(w*uvz+uuvz);
}

// ---------------- frames + head weights ----------------
__global__ void frames_kernel(const float* __restrict__ T, const float* __restrict__ head_weights) {
    int n = blockIdx.x*blockDim.x + threadIdx.x;
    if (n < N_) {
        const float* t = T + n*16;
        float q0=t[0], q1=t[1], q2=t[2], q3=t[3];
        float inv = rsqrtf(q0*q0+q1*q1+q2*q2+q3*q3 + 1e-8f);
        g_qn[n*4+0]=q0*inv; g_qn[n*4+1]=q1*inv; g_qn[n*4+2]=q2*inv; g_qn[n*4+3]=q3*inv;
        g_tr[n*3+0]=t[4]; g_tr[n*3+1]=t[5]; g_tr[n*3+2]=t[6];
    }
    if (n < H_) {
        float x = head_weights[n];
        float sp = (x > 20.f) ? x : log1pf(expf(x));
        g_hw[n] = sp * rsqrtf(108.0f);   // softplus * sqrt(1/(3*36))
    }
}

// ---------------- generic SGEMM: C = A[MxK] @ B[KxN] + bias ----------------
__global__ void sgemm_bias(const float* __restrict__ A, const float* __restrict__ B,
                           const float* __restrict__ bias, float* __restrict__ C,
                           int M, int Ncols, int K) {
    __shared__ float As[16*65];
    __shared__ float Bs[16*65];
    int bm = blockIdx.y*64, bn = blockIdx.x*64;
    int tx = threadIdx.x, ty = threadIdx.y;
    int tid = ty*16+tx;
    float acc[4][4] = {};
    for (int k0=0; k0<K; k0+=16) {
        for (int t=tid; t<1024; t+=256) {
            int kk=t&15, m=t>>4;
            int gm=bm+m, gk=k0+kk;
            As[kk*65+m] = (gm<M) ? A[(size_t)gm*K+gk] : 0.f;
        }
        for (int t=tid; t<1024; t+=256) {
            int nn=t&63, kk=t>>6;
            int gn=bn+nn, gk=k0+kk;
            Bs[kk*65+nn] = (gn<Ncols) ? B[(size_t)gk*Ncols+gn] : 0.f;
        }
        __syncthreads();
        #pragma unroll
        for (int kk=0; kk<16; kk++) {
            float a[4], b[4];
            #pragma unroll
            for (int i=0;i<4;i++) a[i]=As[kk*65+ty*4+i];
            #pragma unroll
            for (int j=0;j<4;j++) b[j]=Bs[kk*65+tx*4+j];
            #pragma unroll
            for (int i=0;i<4;i++)
                #pragma unroll
                for (int j=0;j<4;j++) acc[i][j] += a[i]*b[j];
        }
        __syncthreads();
    }
    #pragma unroll
    for (int i=0;i<4;i++) {
        int gm=bm+ty*4+i;
        if (gm>=M) continue;
        #pragma unroll
        for (int j=0;j<4;j++) {
            int gn=bn+tx*4+j;
            if (gn>=Ncols) continue;
            C[(size_t)gm*Ncols+gn] = acc[i][j] + (bias ? bias[gn] : 0.f);
        }
    }
}

// ---------------- point transforms + Qf/Kf packing ----------------
__global__ void pts_pack_kernel() {
    int n = blockIdx.x, tid = threadIdx.x;   // 128 threads
    __shared__ float sq[64*3], sk[64*3];
    __shared__ float qsq[H_], ksq[H_];
    __shared__ float qn[4], tr[3];
    if (tid<4) qn[tid]=g_qn[n*4+tid];
    if (tid>=4 && tid<7) tr[tid-4]=g_tr[n*3+tid-4];
    if (tid<H_) { qsq[tid]=0.f; ksq[tid]=0.f; }
    __syncthreads();
    if (tid < 64) {
        float p[3], o[3];
        #pragma unroll
        for (int d=0; d<3; d++) p[d]=g_qpl[(size_t)n*192 + d*64 + tid];
        qrot(qn, p, o);
        float ss=0.f;
        #pragma unroll
        for (int d=0; d<3; d++) { o[d]+=tr[d]; sq[tid*3+d]=o[d]; ss+=o[d]*o[d]; }
        atomicAdd(&qsq[tid>>3], ss);
        #pragma unroll
        for (int d=0; d<3; d++) p[d]=g_kpl[(size_t)n*192 + d*64 + tid];
        qrot(qn, p, o);
        ss=0.f;
        #pragma unroll
        for (int d=0; d<3; d++) { o[d]+=tr[d]; sk[tid*3+d]=o[d]; ss+=o[d]*o[d]; }
        atomicAdd(&ksq[tid>>3], ss);
    }
    __syncthreads();
    float s1 = rsqrtf(384.f);   // sqrt(1/(3*C))
    for (int t=tid; t<H_*KF_; t+=128) {
        int h=t/KF_, c=t%KF_;
        float qv, kv;
        if (c < C_) {
            qv = g_q[(size_t)n*1024 + h*C_ + c] * s1;
            kv = g_kv[(size_t)n*2048 + h*256 + c];
        } else if (c < 152) {
            int m=c-128, pp=m/3, d=m%3;
            int idx=(h*PQ_+pp)*3+d;
            qv = sq[idx]*g_hw[h];
            kv = sk[idx];
        } else { qv=0.f; kv=0.f; }
        g_Qf[((size_t)h*N_+n)*KF_ + c] = qv;
        g_Kf[((size_t)h*N_+n)*KF_ + c] = kv;
    }
    if (tid < H_) {
        g_rowc[tid*N_+n] = -0.5f*g_hw[tid]*qsq[tid];
        g_colc[tid*N_+n] = -0.5f*g_hw[tid]*ksq[tid];
    }
}

// ---------------- v_g mix + mv_transform + Vcat assembly ----------------
__global__ void vg_kernel(const float* __restrict__ gin, const float* __restrict__ W_mg) {
    int n = blockIdx.x, tid = threadIdx.x;   // 128 threads
    __shared__ float cat16[16*16];
    __shared__ float mix[64*16];
    __shared__ float qn[4], tr[3];
    if (tid<4) qn[tid]=g_qn[n*4+tid];
    if (tid>=4 && tid<7) tr[tid-4]=g_tr[n*3+tid-4];
    {
        int p=tid>>4, c=tid&15;
        cat16[p*16+c]     = g_vgl[(size_t)n*128 + p*16 + c];
        cat16[(p+8)*16+c] = gin  [(size_t)n*128 + p*16 + c];
    }
    __syncthreads();
    for (int t=tid; t<1024; t+=128) {
        int o=t>>4, c=t&15;
        float acc=0.f;
        #pragma unroll
        for (int i=0;i<16;i++) acc += W_mg[o*16+i]*cat16[i*16+c];
        mix[t]=acc;
    }
    __syncthreads();
    if (tid < 64) {
        int o=tid, h=o>>3, p=o&7;
        float mv[16];
        #pragma unroll
        for (int c=0;c<16;c++) mv[c]=mix[o*16+c];
        float out[16];
        out[0]=mv[0];
        qrot(qn, mv+1, out+1);
        qrot(qn, mv+4, out+4);
        float pv[3]; qrot(qn, mv+7, pv);
        float w=mv[10];
        out[7]=pv[0]+w*tr[0]; out[8]=pv[1]+w*tr[1]; out[9]=pv[2]+w*tr[2];
        #pragma unroll
        for (int c=10;c<16;c++) out[c]=mv[c];
        float* dst = g_Vcat + ((size_t)h*N_+n)*VC_ + 128 + p*16;
        #pragma unroll
        for (int c=0;c<16;c++) dst[c]=out[c];
    }
    for (int t=tid; t<H_*C_; t+=128) {
        int h=t>>7, c=t&127;
        g_Vcat[((size_t)h*N_+n)*VC_ + c] = g_kv[(size_t)n*2048 + h*256 + 128 + c];
    }
    if (tid < H_) {
        float* dst = g_Vcat + ((size_t)tid*N_+n)*VC_ + 256;
        dst[0]=qn[0]; dst[1]=qn[1]; dst[2]=qn[2]; dst[3]=qn[3];
        dst[4]=tr[0]; dst[5]=tr[1]; dst[6]=tr[2]; dst[7]=0.f;
    }
}

// ---------------- fused z pass: z@W_b -> pairb, z@W_dz + b_dz -> zdz ----------------
__global__ void zfuse_kernel(const float* __restrict__ z, const float* __restrict__ W_b,
                             const float* __restrict__ W_dz, const float* __restrict__ b_dz) {
    __shared__ float Ws[128*40];
    __shared__ float zs[64*33];
    int tid = threadIdx.x;  // 256
    size_t p0 = (size_t)blockIdx.x * 64;
    for (int t=tid; t<128*40; t+=256) {
        int k=t/40, c=t%40;
        Ws[t] = (c<8) ? W_b[k*8+c] : W_dz[k*32 + (c-8)];
    }
    float acc[10] = {};
    int r = tid>>2, cg = tid&3;
    for (int k0=0; k0<128; k0+=32) {
        __syncthreads();
        for (int t=tid; t<64*32; t+=256) {
            int rr=t>>5, kk=t&31;
            zs[rr*33+kk] = z[(p0+rr)*128 + k0+kk];
        }
        __syncthreads();
        #pragma unroll
        for (int kk=0; kk<32; kk++) {
            float zv = zs[r*33+kk];
            const float* w = Ws + (k0+kk)*40 + cg*10;
            #pragma unroll
            for (int c=0;c<10;c++) acc[c] += zv*w[c];
        }
    }
    size_t p = p0 + r;
    #pragma unroll
    for (int c=0;c<10;c++) {
        int col = cg*10+c;
        if (col < 8) g_pairb[p*8+col] = acc[c];
        else         g_zdz[p*32 + (col-8)] = acc[c] + b_dz[col-8];
    }
}

// ---------------- per-head logits: Qf @ Kf^T + epilogue ----------------
__global__ void logits_kernel(const float* __restrict__ b_b, const float* __restrict__ sw,
                              const float* __restrict__ mask) {
    int h = blockIdx.z;
    int bi = blockIdx.y*64, bj = blockIdx.x*64;
    const float* Qp = g_Qf + (size_t)h*N_*KF_;
    const float* Kp = g_Kf + (size_t)h*N_*KF_;
    __shared__ float Qs[16*65], Ks[16*65];
    int tx=threadIdx.x, ty=threadIdx.y, tid=ty*16+tx;
    float acc[4][4] = {};
    for (int k0=0; k0<KF_; k0+=16) {
        for (int t=tid; t<1024; t+=256) {
            int kk=t&15, m=t>>4;
            Qs[kk*65+m] = Qp[(size_t)(bi+m)*KF_ + k0+kk];
            Ks[kk*65+m] = Kp[(size_t)(bj+m)*KF_ + k0+kk];
        }
        __syncthreads();
        #pragma unroll
        for (int kk=0; kk<16; kk++) {
            float a[4], b[4];
            #pragma unroll
            for (int i=0;i<4;i++) a[i]=Qs[kk*65+ty*4+i];
            #pragma unroll
            for (int j=0;j<4;j++) b[j]=Ks[kk*65+tx*4+j];
            #pragma unroll
            for (int i=0;i<4;i++)
                #pragma unroll
                for (int j=0;j<4;j++) acc[i][j] += a[i]*b[j];
        }
        __syncthreads();
    }
    const float s2 = 0.57735026918962576f;  // sqrt(1/3)
    float swh = sw[h], bbh = b_b[h];
    #pragma unroll
    for (int i=0;i<4;i++) {
        int gi = bi+ty*4+i;
        float rc = g_rowc[h*N_+gi];
        float mi = mask[gi];
        #pragma unroll
        for (int j=0;j<4;j++) {
            int gj = bj+tx*4+j;
            float v = acc[i][j] + rc + g_colc[h*N_+gj]
                    + s2*(g_pairb[((size_t)gi*N_+gj)*H_ + h] + bbh)
                    + 100000.0f*(mi*mask[gj]-1.0f);
            g_A[((size_t)h*N_+gi)*N_ + gj] = v*swh;
        }
    }
}

// ---------------- row softmax over j (rows of length 512) ----------------
__global__ void softmax_kernel() {
    int row = blockIdx.x;  // h*N_ + i
    float* a = g_A + (size_t)row*N_;
    int tid = threadIdx.x;  // 256
    __shared__ float red[256];
    float v0=a[tid], v1=a[tid+256];
    red[tid]=fmaxf(v0,v1);
    __syncthreads();
    for (int s=128; s>0; s>>=1) { if (tid<s) red[tid]=fmaxf(red[tid],red[tid+s]); __syncthreads(); }
    float m = red[0];
    __syncthreads();
    float e0=expf(v0-m), e1=expf(v1-m);
    red[tid]=e0+e1;
    __syncthreads();
    for (int s=128; s>0; s>>=1) { if (tid<s) red[tid]+=red[tid+s]; __syncthreads(); }
    float inv = 1.f/red[0];
    a[tid]     = e0*inv;
    a[tid+256] = e1*inv;
}

// ---------------- per-head A @ Vcat ----------------
__global__ void av_kernel() {
    int h = blockIdx.z;
    int bi = blockIdx.y*64, bc = blockIdx.x*64;
    const float* Ap = g_A    + (size_t)h*N_*N_;
    const float* Bp = g_Vcat + (size_t)h*N_*VC_;
    __shared__ float As[16*65], Bs[16*65];
    int tx=threadIdx.x, ty=threadIdx.y, tid=ty*16+tx;
    float acc[4][4] = {};
    for (int k0=0; k0<N_; k0+=16) {
        for (int t=tid; t<1024; t+=256) {
            int kk=t&15, m=t>>4;
            As[kk*65+m] = Ap[(size_t)(bi+m)*N_ + k0+kk];
        }
        for (int t=tid; t<1024; t+=256) {
            int nn=t&63, kk=t>>6;
            int gc=bc+nn;
            Bs[kk*65+nn] = (gc<VC_) ? Bp[(size_t)(k0+kk)*VC_ + gc] : 0.f;
        }
        __syncthreads();
        #pragma unroll
        for (int kk=0; kk<16; kk++) {
            float a[4], b[4];
            #pragma unroll
            for (int i=0;i<4;i++) a[i]=As[kk*65+ty*4+i];
            #pragma unroll
            for (int j=0;j<4;j++) b[j]=Bs[kk*65+tx*4+j];
            #pragma unroll
            for (int i=0;i<4;i++)
                #pragma unroll
                for (int j=0;j<4;j++) acc[i][j] += a[i]*b[j];
        }
        __syncthreads();
    }
    #pragma unroll
    for (int i=0;i<4;i++) {
        int gi=bi+ty*4+i;
        #pragma unroll
        for (int j=0;j<4;j++) {
            int gc=bc+tx*4+j;
            if (gc<VC_) g_Ocat[((size_t)h*N_+gi)*VC_ + gc] = acc[i][j];
        }
    }
}

// ---------------- o_pair[i,h,c] = sum_j A[h,i,j] * zdz[i,j,c] ----------------
__global__ void opair_kernel() {
    int i = blockIdx.x;
    int tid = threadIdx.x;  // 256
    __shared__ float Zs[64*33];
    __shared__ float Asm[8*64];
    int hh = tid>>5, cc = tid&31;
    float acc = 0.f;
    for (int jt=0; jt<N_; jt+=64) {
        __syncthreads();
        for (int t=tid; t<2048; t+=256) {
            int jj=t>>5, c=t&31;
            Zs[jj*33+c] = g_zdz[((size_t)i*N_ + jt+jj)*32 + c];
        }
        for (int t=tid; t<512; t+=256) {
            int h=t>>6, jj=t&63;
            Asm[h*64+jj] = g_A[((size_t)h*N_+i)*N_ + jt+jj];
        }
        __syncthreads();
        #pragma unroll
        for (int jj=0; jj<64; jj++) acc += Asm[hh*64+jj]*Zs[jj*33+cc];
    }
    g_feats[(size_t)i*FEAT_ + hh*SEG_ + cc] = acc;
}

// ---------------- finalize: inv transform, norms, o_rel, feats assembly ----------------
__global__ void finalize_kernel() {
    int n = blockIdx.x, tid = threadIdx.x;  // 128
    __shared__ float qn[4], tr[3];
    if (tid<4) qn[tid]=g_qn[n*4+tid];
    if (tid>=4 && tid<7) tr[tid-4]=g_tr[n*3+tid-4];
    __syncthreads();
    for (int t=tid; t<H_*C_; t+=128) {
        int h=t>>7, c=t&127;
        g_feats[(size_t)n*FEAT_ + h*SEG_ + 32 + c] = g_Ocat[((size_t)h*N_+n)*VC_ + c];
    }
    if (tid < 64) {
        int h=tid>>3, p=tid&7;
        const float* oc = g_Ocat + ((size_t)h*N_+n)*VC_ + 128 + p*16;
        float mv[16];
        #pragma unroll
        for (int c=0;c<16;c++) mv[c]=oc[c];
        float qc[4] = {qn[0], -qn[1], -qn[2], -qn[3]};
        float out[16];
        out[0]=mv[0];
        qrot(qc, mv+1, out+1);
        qrot(qc, mv+4, out+4);
        float w=mv[10];
        float tmp[3] = {mv[7]-w*tr[0], mv[8]-w*tr[1], mv[9]-w*tr[2]};
        qrot(qc, tmp, out+7);
        #pragma unroll
        for (int c=10;c<16;c++) out[c]=mv[c];
        float s1v=1e-8f, s2v=1e-8f;
        #pragma unroll
        for (int c=0;c<10;c++) s1v += out[c]*out[c];
        #pragma unroll
        for (int c=10;c<16;c++) s2v += out[c]*out[c];
        float* f = g_feats + (size_t)n*FEAT_ + h*SEG_;
        #pragma unroll
        for (int c=0;c<16;c++) f[168+p*16+c]=out[c];
        f[296+p*2+0]=sqrtf(s1v);
        f[296+p*2+1]=sqrtf(s2v);
    }
    if (tid < H_) {
        int h=tid;
        const float* oc = g_Ocat + ((size_t)h*N_+n)*VC_;
        float aq0=oc[256], aq1=oc[257], aq2=oc[258], aq3=oc[259];
        float qc[4] = {qn[0], -qn[1], -qn[2], -qn[3]};
        float qr0 = qc[0]*aq0 - qc[1]*aq1 - qc[2]*aq2 - qc[3]*aq3;
        float qr1 = qc[0]*aq1 + qc[1]*aq0 + qc[2]*aq3 - qc[3]*aq2;
        float qr2 = qc[0]*aq2 - qc[1]*aq3 + qc[2]*aq0 + qc[3]*aq1;
        float qr3 = qc[0]*aq3 + qc[1]*aq2 - qc[2]*aq1 + qc[3]*aq0;
        float d[3] = {oc[260]-tr[0], oc[261]-tr[1], oc[262]-tr[2]};
        float trel[3];
        qrot(qc, d, trel);
        float* f = g_feats + (size_t)n*FEAT_ + h*SEG_ + 160;
        f[0]=qr0; f[1]=qr1; f[2]=qr2; f[3]=qr3;
        f[4]=trel[0]; f[5]=trel[1]; f[6]=trel[2]; f[7]=0.f;
    }
}

// ---------------- g_out = W_geo mix over (h,p) ----------------
__global__ void gout_kernel(const float* __restrict__ W_geo, float* __restrict__ out) {
    int n = blockIdx.x, tid = threadIdx.x;  // 128
    int o = tid>>4, c = tid&15;
    float acc = 0.f;
    #pragma unroll
    for (int i2=0; i2<64; i2++) {
        acc += W_geo[o*64+i2] * g_feats[(size_t)n*FEAT_ + (i2>>3)*SEG_ + 168 + (i2&7)*16 + c];
    }
    out[(size_t)n*128 + o*16 + c] = acc;
}

// ---------------- launch ----------------
extern "C" void kernel_launch(void* const* d_in, const int* in_sizes, int n_in,
                              void* d_out, int out_size) {
    const float* s    = (const float*)d_in[0];
    const float* gin  = (const float*)d_in[1];
    const float* z    = (const float*)d_in[2];
    const float* T    = (const float*)d_in[3];
    const float* mask = (const float*)d_in[4];
    const float* W_q  = (const float*)d_in[5];
    const float* b_q  = (const float*)d_in[6];
    const float* W_kv = (const float*)d_in[7];
    const float* b_kv = (const float*)d_in[8];
    const float* W_qp = (const float*)d_in[9];
    const float* b_qp = (const float*)d_in[10];
    const float* W_kp = (const float*)d_in[11];
    const float* b_kp = (const float*)d_in[12];
    const float* W_vg = (const float*)d_in[13];
    const float* b_vg = (const float*)d_in[14];
    const float* W_mg = (const float*)d_in[15];
    const float* W_b  = (const float*)d_in[16];
    const float* b_b  = (const float*)d_in[17];
    const float* W_dz = (const float*)d_in[18];
    const float* b_dz = (const float*)d_in[19];
    const float* head_weights    = (const float*)d_in[20];
    const float* softmax_weights = (const float*)d_in[21];
    const float* W_out = (const float*)d_in[22];
    const float* b_out = (const float*)d_in[23];
    const float* W_geo = (const float*)d_in[24];
    float* out = (float*)d_out;

    float *pq, *pkv, *pqpl, *pkpl, *pvgl, *pfeats;
    cudaGetSymbolAddress((void**)&pq,    g_q);
    cudaGetSymbolAddress((void**)&pkv,   g_kv);
    cudaGetSymbolAddress((void**)&pqpl,  g_qpl);
    cudaGetSymbolAddress((void**)&pkpl,  g_kpl);
    cudaGetSymbolAddress((void**)&pvgl,  g_vgl);
    cudaGetSymbolAddress((void**)&pfeats,g_feats);

    dim3 thr(16,16);

    frames_kernel<<<2,256>>>(T, head_weights);

    sgemm_bias<<<dim3(1024/64, 512/64), thr>>>(s, W_q,  b_q,  pq,   512, 1024, 384);
    sgemm_bias<<<dim3(2048/64, 8),      thr>>>(s, W_kv, b_kv, pkv,  512, 2048, 384);
    sgemm_bias<<<dim3(3, 8),            thr>>>(s, W_qp, b_qp, pqpl, 512, 192,  384);
    sgemm_bias<<<dim3(3, 8),            thr>>>(s, W_kp, b_kp, pkpl, 512, 192,  384);
    sgemm_bias<<<dim3(2, 8),            thr>>>(s, W_vg, b_vg, pvgl, 512, 128,  384);

    pts_pack_kernel<<<512,128>>>();
    vg_kernel<<<512,128>>>(gin, W_mg);
    zfuse_kernel<<<4096,256>>>(z, W_b, W_dz, b_dz);

    logits_kernel<<<dim3(8,8,8), thr>>>(b_b, softmax_weights, mask);
    softmax_kernel<<<4096,256>>>();
    av_kernel<<<dim3(5,8,8), thr>>>();
    opair_kernel<<<512,256>>>();
    finalize_kernel<<<512,128>>>();

    sgemm_bias<<<dim3(6,8), thr>>>(pfeats, W_out, b_out, out, 512, 384, 2496);
    gout_kernel<<<512,128>>>(W_geo, out + 512*384);
}

// round 2
// speedup vs baseline: 3.6271x; 3.6271x over previous
#include <cuda_runtime.h>
#include <math.h>

#define N_    512
#define H_    8
#define C_    128
#define PQ_   8
#define PV_   8
#define KF_   160   // 128 (q/k) + 24 (pts) padded to 160
#define VCP_  384   // padded Vcat/Ocat stride (logical 264)
#define SEG_  312
#define FEAT_ 2496
#define PROJ_ 3584  // 1024 + 2048 + 192 + 192 + 128

// ---------------- scratch ----------------
static __device__ float g_Wcat[384*PROJ_];
static __device__ float g_bcat[PROJ_];
static __device__ float g_proj[(size_t)N_*PROJ_];
static __device__ float g_Qf[(size_t)H_*N_*KF_];
static __device__ float g_Kf[(size_t)H_*N_*KF_];
static __device__ float g_rowc[H_*N_];
static __device__ float g_colc[H_*N_];
static __device__ float g_qn[N_*4];
static __device__ float g_tr[N_*3];
static __device__ float g_hw[H_];
static __device__ float g_pairb[(size_t)N_*N_*H_];
static __device__ float g_zdz[(size_t)N_*N_*32];
static __device__ float g_A[(size_t)H_*N_*N_];
static __device__ float g_Vcat[(size_t)H_*N_*VCP_];
static __device__ float g_Ocat[(size_t)H_*N_*VCP_];
static __device__ float g_feats[(size_t)N_*FEAT_];

// ---------------- helpers ----------------
__device__ __forceinline__ void qrot(const float* q, const float* v, float* o) {
    float w=q[0], x=q[1], y=q[2], z=q[3];
    float uvx = y*v[2]-z*v[1];
    float uvy = z*v[0]-x*v[2];
    float uvz = x*v[1]-y*v[0];
    float uuvx = y*uvz-z*uvy;
    float uuvy = z*uvx-x*uvz;
    float uuvz = x*uvy-y*uvx;
    o[0]=v[0]+2.f*(w*uvx+uuvx);
    o[1]=v[1]+2.f*(w*uvy+uuvy);
    o[2]=v[2]+2.f*(w*uvz+uuvz);
}

// ---------------- frames + head weights ----------------
__global__ void frames_kernel(const float* __restrict__ T, const float* __restrict__ head_weights) {
    int n = blockIdx.x*blockDim.x + threadIdx.x;
    if (n < N_) {
        const float* t = T + n*16;
        float q0=t[0], q1=t[1], q2=t[2], q3=t[3];
        float inv = rsqrtf(q0*q0+q1*q1+q2*q2+q3*q3 + 1e-8f);
        g_qn[n*4+0]=q0*inv; g_qn[n*4+1]=q1*inv; g_qn[n*4+2]=q2*inv; g_qn[n*4+3]=q3*inv;
        g_tr[n*3+0]=t[4]; g_tr[n*3+1]=t[5]; g_tr[n*3+2]=t[6];
    }
    if (n < H_) {
        float x = head_weights[n];
        float sp = (x > 20.f) ? x : log1pf(expf(x));
        g_hw[n] = sp * rsqrtf(108.0f);
    }
}

// ---------------- weight packing ----------------
__global__ void pack_kernel(const float* __restrict__ W_q, const float* __restrict__ W_kv,
                            const float* __restrict__ W_qp, const float* __restrict__ W_kp,
                            const float* __restrict__ W_vg,
                            const float* __restrict__ b_q, const float* __restrict__ b_kv,
                            const float* __restrict__ b_qp, const float* __restrict__ b_kp,
                            const float* __restrict__ b_vg) {
    int idx = blockIdx.x*256 + threadIdx.x;
    if (idx >= 384*PROJ_) return;
    int k = idx / PROJ_, c = idx % PROJ_;
    float v;
    if      (c < 1024) v = W_q [k*1024 + c];
    else if (c < 3072) v = W_kv[k*2048 + (c-1024)];
    else if (c < 3264) v = W_qp[k*192  + (c-3072)];
    else if (c < 3456) v = W_kp[k*192  + (c-3264)];
    else               v = W_vg[k*128  + (c-3456)];
    g_Wcat[idx] = v;
    if (k == 0) {
        float b;
        if      (c < 1024) b = b_q [c];
        else if (c < 3072) b = b_kv[c-1024];
        else if (c < 3264) b = b_qp[c-3072];
        else if (c < 3456) b = b_kp[c-3264];
        else               b = b_vg[c-3456];
        g_bcat[c] = b;
    }
}

// ---------------- 128x128x16 SGEMM, 8x8/thread, exact tiles ----------------
__global__ void __launch_bounds__(256) sgemm128(const float* __restrict__ A, const float* __restrict__ B,
                                                const float* __restrict__ bias, float* __restrict__ C,
                                                int Ncols, int K) {
    __shared__ float As[16][132];
    __shared__ float Bs[16][132];
    int bm = blockIdx.y*128, bn = blockIdx.x*128;
    int tid = threadIdx.x;
    int tx = tid & 15, ty = tid >> 4;
    int ar = tid >> 1, ac = (tid & 1) * 8;
    int br = tid >> 4, bc = (tid & 15) * 8;
    float acc[8][8] = {};
    for (int k0 = 0; k0 < K; k0 += 16) {
        const float* Ap = A + (size_t)(bm+ar)*K + k0 + ac;
        float4 a0 = *(const float4*)Ap;
        float4 a1 = *(const float4*)(Ap+4);
        As[ac+0][ar]=a0.x; As[ac+1][ar]=a0.y; As[ac+2][ar]=a0.z; As[ac+3][ar]=a0.w;
        As[ac+4][ar]=a1.x; As[ac+5][ar]=a1.y; As[ac+6][ar]=a1.z; As[ac+7][ar]=a1.w;
        const float* Bp = B + (size_t)(k0+br)*Ncols + bn + bc;
        *(float4*)&Bs[br][bc]   = *(const float4*)Bp;
        *(float4*)&Bs[br][bc+4] = *(const float4*)(Bp+4);
        __syncthreads();
        #pragma unroll
        for (int kk = 0; kk < 16; kk++) {
            float a[8], b[8];
            *(float4*)a     = *(float4*)&As[kk][ty*8];
            *(float4*)(a+4) = *(float4*)&As[kk][ty*8+4];
            *(float4*)b     = *(float4*)&Bs[kk][tx*8];
            *(float4*)(b+4) = *(float4*)&Bs[kk][tx*8+4];
            #pragma unroll
            for (int i=0;i<8;i++)
                #pragma unroll
                for (int j=0;j<8;j++) acc[i][j] += a[i]*b[j];
        }
        __syncthreads();
    }
    #pragma unroll
    for (int i=0;i<8;i++) {
        int gm = bm + ty*8 + i;
        #pragma unroll
        for (int j=0;j<8;j++) {
            int gn = bn + tx*8 + j;
            C[(size_t)gm*Ncols + gn] = acc[i][j] + (bias ? bias[gn] : 0.f);
        }
    }
}

// ---------------- split-K SGEMM with atomic accumulation ----------------
__global__ void __launch_bounds__(256) sgemm_splitk(const float* __restrict__ A, const float* __restrict__ B,
                                                    float* __restrict__ C, int Ncols, int Astride, int KS) {
    __shared__ float As[16][132];
    __shared__ float Bs[16][132];
    int bm = blockIdx.y*128, bn = blockIdx.x*128;
    int kstart = blockIdx.z * KS;
    int tid = threadIdx.x;
    int tx = tid & 15, ty = tid >> 4;
    int ar = tid >> 1, ac = (tid & 1) * 8;
    int br = tid >> 4, bc = (tid & 15) * 8;
    float acc[8][8] = {};
    for (int k0 = kstart; k0 < kstart + KS; k0 += 16) {
        const float* Ap = A + (size_t)(bm+ar)*Astride + k0 + ac;
        float4 a0 = *(const float4*)Ap;
        float4 a1 = *(const float4*)(Ap+4);
        As[ac+0][ar]=a0.x; As[ac+1][ar]=a0.y; As[ac+2][ar]=a0.z; As[ac+3][ar]=a0.w;
        As[ac+4][ar]=a1.x; As[ac+5][ar]=a1.y; As[ac+6][ar]=a1.z; As[ac+7][ar]=a1.w;
        const float* Bp = B + (size_t)(k0+br)*Ncols + bn + bc;
        *(float4*)&Bs[br][bc]   = *(const float4*)Bp;
        *(float4*)&Bs[br][bc+4] = *(const float4*)(Bp+4);
        __syncthreads();
        #pragma unroll
        for (int kk = 0; kk < 16; kk++) {
            float a[8], b[8];
            *(float4*)a     = *(float4*)&As[kk][ty*8];
            *(float4*)(a+4) = *(float4*)&As[kk][ty*8+4];
            *(float4*)b     = *(float4*)&Bs[kk][tx*8];
            *(float4*)(b+4) = *(float4*)&Bs[kk][tx*8+4];
            #pragma unroll
            for (int i=0;i<8;i++)
                #pragma unroll
                for (int j=0;j<8;j++) acc[i][j] += a[i]*b[j];
        }
        __syncthreads();
    }
    #pragma unroll
    for (int i=0;i<8;i++) {
        int gm = bm + ty*8 + i;
        #pragma unroll
        for (int j=0;j<8;j++) {
            int gn = bn + tx*8 + j;
            atomicAdd(&C[(size_t)gm*Ncols + gn], acc[i][j]);
        }
    }
}

// ---------------- per-head A @ Vcat, split-K=2, atomic ----------------
__global__ void __launch_bounds__(256) av_kernel() {
    int hz = blockIdx.z;
    int h = hz >> 1, sp = hz & 1;
    const float* A = g_A    + (size_t)h*N_*N_;
    const float* B = g_Vcat + (size_t)h*N_*VCP_;
    float*       C = g_Ocat + (size_t)h*N_*VCP_;
    __shared__ float As[16][132];
    __shared__ float Bs[16][132];
    int bm = blockIdx.y*128, bn = blockIdx.x*128;
    int tid = threadIdx.x;
    int tx = tid & 15, ty = tid >> 4;
    int ar = tid >> 1, ac = (tid & 1) * 8;
    int br = tid >> 4, bc = (tid & 15) * 8;
    float acc[8][8] = {};
    int kstart = sp * 256;
    for (int k0 = kstart; k0 < kstart + 256; k0 += 16) {
        const float* Ap = A + (size_t)(bm+ar)*N_ + k0 + ac;
        float4 a0 = *(const float4*)Ap;
        float4 a1 = *(const float4*)(Ap+4);
        As[ac+0][ar]=a0.x; As[ac+1][ar]=a0.y; As[ac+2][ar]=a0.z; As[ac+3][ar]=a0.w;
        As[ac+4][ar]=a1.x; As[ac+5][ar]=a1.y; As[ac+6][ar]=a1.z; As[ac+7][ar]=a1.w;
        const float* Bp = B + (size_t)(k0+br)*VCP_ + bn + bc;
        *(float4*)&Bs[br][bc]   = *(const float4*)Bp;
        *(float4*)&Bs[br][bc+4] = *(const float4*)(Bp+4);
        __syncthreads();
        #pragma unroll
        for (int kk = 0; kk < 16; kk++) {
            float a[8], b[8];
            *(float4*)a     = *(float4*)&As[kk][ty*8];
            *(float4*)(a+4) = *(float4*)&As[kk][ty*8+4];
            *(float4*)b     = *(float4*)&Bs[kk][tx*8];
            *(float4*)(b+4) = *(float4*)&Bs[kk][tx*8+4];
            #pragma unroll
            for (int i=0;i<8;i++)
                #pragma unroll
                for (int j=0;j<8;j++) acc[i][j] += a[i]*b[j];
        }
        __syncthreads();
    }
    #pragma unroll
    for (int i=0;i<8;i++) {
        int gm = bm + ty*8 + i;
        #pragma unroll
        for (int j=0;j<8;j++) {
            int gn = bn + tx*8 + j;
            atomicAdd(&C[(size_t)gm*VCP_ + gn], acc[i][j]);
        }
    }
}

// ---------------- per-head logits: Qf @ Kf^T + epilogue, 128x128 ----------------
__global__ void __launch_bounds__(256) logits_kernel(const float* __restrict__ b_b,
                                                     const float* __restrict__ sw,
                                                     const float* __restrict__ mask) {
    int h = blockIdx.z;
    int bi = blockIdx.y*128, bj = blockIdx.x*128;
    const float* Qp = g_Qf + (size_t)h*N_*KF_;
    const float* Kp = g_Kf + (size_t)h*N_*KF_;
    __shared__ float Qs[16][132];
    __shared__ float Ks[16][132];
    int tid = threadIdx.x;
    int tx = tid & 15, ty = tid >> 4;
    int ar = tid >> 1, ac = (tid & 1) * 8;
    float acc[8][8] = {};
    for (int k0 = 0; k0 < KF_; k0 += 16) {
        const float* qp = Qp + (size_t)(bi+ar)*KF_ + k0 + ac;
        float4 a0 = *(const float4*)qp;
        float4 a1 = *(const float4*)(qp+4);
        Qs[ac+0][ar]=a0.x; Qs[ac+1][ar]=a0.y; Qs[ac+2][ar]=a0.z; Qs[ac+3][ar]=a0.w;
        Qs[ac+4][ar]=a1.x; Qs[ac+5][ar]=a1.y; Qs[ac+6][ar]=a1.z; Qs[ac+7][ar]=a1.w;
        const float* kp = Kp + (size_t)(bj+ar)*KF_ + k0 + ac;
        float4 b0 = *(const float4*)kp;
        float4 b1 = *(const float4*)(kp+4);
        Ks[ac+0][ar]=b0.x; Ks[ac+1][ar]=b0.y; Ks[ac+2][ar]=b0.z; Ks[ac+3][ar]=b0.w;
        Ks[ac+4][ar]=b1.x; Ks[ac+5][ar]=b1.y; Ks[ac+6][ar]=b1.z; Ks[ac+7][ar]=b1.w;
        __syncthreads();
        #pragma unroll
        for (int kk = 0; kk < 16; kk++) {
            float a[8], b[8];
            *(float4*)a     = *(float4*)&Qs[kk][ty*8];
            *(float4*)(a+4) = *(float4*)&Qs[kk][ty*8+4];
            *(float4*)b     = *(float4*)&Ks[kk][tx*8];
            *(float4*)(b+4) = *(float4*)&Ks[kk][tx*8+4];
            #pragma unroll
            for (int i=0;i<8;i++)
                #pragma unroll
                for (int j=0;j<8;j++) acc[i][j] += a[i]*b[j];
        }
        __syncthreads();
    }
    const float s2 = 0.57735026918962576f;
    float swh = sw[h], bbh = b_b[h];
    #pragma unroll
    for (int i=0;i<8;i++) {
        int gi = bi + ty*8 + i;
        float rc = g_rowc[h*N_+gi];
        float mi = mask[gi];
        #pragma unroll
        for (int j=0;j<8;j++) {
            int gj = bj + tx*8 + j;
            float v = acc[i][j] + rc + g_colc[h*N_+gj]
                    + s2*(g_pairb[((size_t)gi*N_+gj)*H_ + h] + bbh)
                    + 100000.0f*(mi*mask[gj]-1.0f);
            g_A[((size_t)h*N_+gi)*N_ + gj] = v*swh;
        }
    }
}

// ---------------- point transforms + Qf/Kf packing ----------------
__global__ void pts_pack_kernel() {
    int n = blockIdx.x, tid = threadIdx.x;   // 128 threads
    __shared__ float sq[64*3], sk[64*3];
    __shared__ float qsq[H_], ksq[H_];
    __shared__ float qn[4], tr[3];
    if (tid<4) qn[tid]=g_qn[n*4+tid];
    if (tid>=4 && tid<7) tr[tid-4]=g_tr[n*3+tid-4];
    if (tid<H_) { qsq[tid]=0.f; ksq[tid]=0.f; }
    __syncthreads();
    if (tid < 64) {
        float p[3], o[3];
        #pragma unroll
        for (int d=0; d<3; d++) p[d]=g_proj[(size_t)n*PROJ_ + 3072 + d*64 + tid];
        qrot(qn, p, o);
        float ss=0.f;
        #pragma unroll
        for (int d=0; d<3; d++) { o[d]+=tr[d]; sq[tid*3+d]=o[d]; ss+=o[d]*o[d]; }
        atomicAdd(&qsq[tid>>3], ss);
        #pragma unroll
        for (int d=0; d<3; d++) p[d]=g_proj[(size_t)n*PROJ_ + 3264 + d*64 + tid];
        qrot(qn, p, o);
        ss=0.f;
        #pragma unroll
        for (int d=0; d<3; d++) { o[d]+=tr[d]; sk[tid*3+d]=o[d]; ss+=o[d]*o[d]; }
        atomicAdd(&ksq[tid>>3], ss);
    }
    __syncthreads();
    float s1 = rsqrtf(384.f);
    for (int t=tid; t<H_*KF_; t+=128) {
        int h=t/KF_, c=t%KF_;
        float qv, kv;
        if (c < C_) {
            qv = g_proj[(size_t)n*PROJ_ + h*C_ + c] * s1;
            kv = g_proj[(size_t)n*PROJ_ + 1024 + h*256 + c];
        } else if (c < 152) {
            int m=c-128, pp=m/3, d=m%3;
            int idx=(h*PQ_+pp)*3+d;
            qv = sq[idx]*g_hw[h];
            kv = sk[idx];
        } else { qv=0.f; kv=0.f; }
        g_Qf[((size_t)h*N_+n)*KF_ + c] = qv;
        g_Kf[((size_t)h*N_+n)*KF_ + c] = kv;
    }
    if (tid < H_) {
        g_rowc[tid*N_+n] = -0.5f*g_hw[tid]*qsq[tid];
        g_colc[tid*N_+n] = -0.5f*g_hw[tid]*ksq[tid];
    }
}

// ---------------- zero scratch (Vcat padding + Ocat accumulators) ----------------
__global__ void zero_kernel() {
    size_t idx = (size_t)blockIdx.x*256 + threadIdx.x;
    size_t tot = (size_t)H_*N_*VCP_;
    if (idx < tot) { g_Vcat[idx] = 0.f; g_Ocat[idx] = 0.f; }
}

// ---------------- v_g mix + mv_transform + Vcat assembly ----------------
__global__ void vg_kernel(const float* __restrict__ gin, const float* __restrict__ W_mg) {
    int n = blockIdx.x, tid = threadIdx.x;   // 128 threads
    __shared__ float cat16[16*16];
    __shared__ float mix[64*16];
    __shared__ float qn[4], tr[3];
    if (tid<4) qn[tid]=g_qn[n*4+tid];
    if (tid>=4 && tid<7) tr[tid-4]=g_tr[n*3+tid-4];
    {
        int p=tid>>4, c=tid&15;
        cat16[p*16+c]     = g_proj[(size_t)n*PROJ_ + 3456 + p*16 + c];
        cat16[(p+8)*16+c] = gin  [(size_t)n*128 + p*16 + c];
    }
    __syncthreads();
    for (int t=tid; t<1024; t+=128) {
        int o=t>>4, c=t&15;
        float acc=0.f;
        #pragma unroll
        for (int i=0;i<16;i++) acc += W_mg[o*16+i]*cat16[i*16+c];
        mix[t]=acc;
    }
    __syncthreads();
    if (tid < 64) {
        int o=tid, h=o>>3, p=o&7;
        float mv[16];
        #pragma unroll
        for (int c=0;c<16;c++) mv[c]=mix[o*16+c];
        float out[16];
        out[0]=mv[0];
        qrot(qn, mv+1, out+1);
        qrot(qn, mv+4, out+4);
        float pv[3]; qrot(qn, mv+7, pv);
        float w=mv[10];
        out[7]=pv[0]+w*tr[0]; out[8]=pv[1]+w*tr[1]; out[9]=pv[2]+w*tr[2];
        #pragma unroll
        for (int c=10;c<16;c++) out[c]=mv[c];
        float* dst = g_Vcat + ((size_t)h*N_+n)*VCP_ + 128 + p*16;
        #pragma unroll
        for (int c=0;c<16;c++) dst[c]=out[c];
    }
    for (int t=tid; t<H_*C_; t+=128) {
        int h=t>>7, c=t&127;
        g_Vcat[((size_t)h*N_+n)*VCP_ + c] = g_proj[(size_t)n*PROJ_ + 1024 + h*256 + 128 + c];
    }
    if (tid < H_) {
        float* dst = g_Vcat + ((size_t)tid*N_+n)*VCP_ + 256;
        dst[0]=qn[0]; dst[1]=qn[1]; dst[2]=qn[2]; dst[3]=qn[3];
        dst[4]=tr[0]; dst[5]=tr[1]; dst[6]=tr[2]; dst[7]=0.f;
    }
}

// ---------------- fused z pass ----------------
__global__ void zfuse_kernel(const float* __restrict__ z, const float* __restrict__ W_b,
                             const float* __restrict__ W_dz, const float* __restrict__ b_dz) {
    __shared__ float Ws[128*40];
    __shared__ float zs[64*33];
    int tid = threadIdx.x;  // 256
    size_t p0 = (size_t)blockIdx.x * 64;
    for (int t=tid; t<128*40; t+=256) {
        int k=t/40, c=t%40;
        Ws[t] = (c<8) ? W_b[k*8+c] : W_dz[k*32 + (c-8)];
    }
    float acc[10] = {};
    int r = tid>>2, cg = tid&3;
    for (int k0=0; k0<128; k0+=32) {
        __syncthreads();
        for (int t=tid; t<64*32; t+=256) {
            int rr=t>>5, kk=t&31;
            zs[rr*33+kk] = z[(p0+rr)*128 + k0+kk];
        }
        __syncthreads();
        #pragma unroll
        for (int kk=0; kk<32; kk++) {
            float zv = zs[r*33+kk];
            const float* w = Ws + (k0+kk)*40 + cg*10;
            #pragma unroll
            for (int c=0;c<10;c++) acc[c] += zv*w[c];
        }
    }
    size_t p = p0 + r;
    #pragma unroll
    for (int c=0;c<10;c++) {
        int col = cg*10+c;
        if (col < 8) g_pairb[p*8+col] = acc[c];
        else         g_zdz[p*32 + (col-8)] = acc[c] + b_dz[col-8];
    }
}

// ---------------- row softmax ----------------
__global__ void softmax_kernel() {
    int row = blockIdx.x;
    float* a = g_A + (size_t)row*N_;
    int tid = threadIdx.x;  // 256
    __shared__ float red[256];
    float v0=a[tid], v1=a[tid+256];
    red[tid]=fmaxf(v0,v1);
    __syncthreads();
    for (int s=128; s>0; s>>=1) { if (tid<s) red[tid]=fmaxf(red[tid],red[tid+s]); __syncthreads(); }
    float m = red[0];
    __syncthreads();
    float e0=expf(v0-m), e1=expf(v1-m);
    red[tid]=e0+e1;
    __syncthreads();
    for (int s=128; s>0; s>>=1) { if (tid<s) red[tid]+=red[tid+s]; __syncthreads(); }
    float inv = 1.f/red[0];
    a[tid]     = e0*inv;
    a[tid+256] = e1*inv;
}

// ---------------- o_pair ----------------
__global__ void opair_kernel() {
    int i = blockIdx.x;
    int tid = threadIdx.x;  // 256
    __shared__ float Zs[64*33];
    __shared__ float Asm[8*64];
    int hh = tid>>5, cc = tid&31;
    float acc = 0.f;
    for (int jt=0; jt<N_; jt+=64) {
        __syncthreads();
        for (int t=tid; t<2048; t+=256) {
            int jj=t>>5, c=t&31;
            Zs[jj*33+c] = g_zdz[((size_t)i*N_ + jt+jj)*32 + c];
        }
        for (int t=tid; t<512; t+=256) {
            int h=t>>6, jj=t&63;
            Asm[h*64+jj] = g_A[((size_t)h*N_+i)*N_ + jt+jj];
        }
        __syncthreads();
        #pragma unroll
        for (int jj=0; jj<64; jj++) acc += Asm[hh*64+jj]*Zs[jj*33+cc];
    }
    g_feats[(size_t)i*FEAT_ + hh*SEG_ + cc] = acc;
}

// ---------------- finalize ----------------
__global__ void finalize_kernel() {
    int n = blockIdx.x, tid = threadIdx.x;  // 128
    __shared__ float qn[4], tr[3];
    if (tid<4) qn[tid]=g_qn[n*4+tid];
    if (tid>=4 && tid<7) tr[tid-4]=g_tr[n*3+tid-4];
    __syncthreads();
    for (int t=tid; t<H_*C_; t+=128) {
        int h=t>>7, c=t&127;
        g_feats[(size_t)n*FEAT_ + h*SEG_ + 32 + c] = g_Ocat[((size_t)h*N_+n)*VCP_ + c];
    }
    if (tid < 64) {
        int h=tid>>3, p=tid&7;
        const float* oc = g_Ocat + ((size_t)h*N_+n)*VCP_ + 128 + p*16;
        float mv[16];
        #pragma unroll
        for (int c=0;c<16;c++) mv[c]=oc[c];
        float qc[4] = {qn[0], -qn[1], -qn[2], -qn[3]};
        float out[16];
        out[0]=mv[0];
        qrot(qc, mv+1, out+1);
        qrot(qc, mv+4, out+4);
        float w=mv[10];
        float tmp[3] = {mv[7]-w*tr[0], mv[8]-w*tr[1], mv[9]-w*tr[2]};
        qrot(qc, tmp, out+7);
        #pragma unroll
        for (int c=10;c<16;c++) out[c]=mv[c];
        float s1v=1e-8f, s2v=1e-8f;
        #pragma unroll
        for (int c=0;c<10;c++) s1v += out[c]*out[c];
        #pragma unroll
        for (int c=10;c<16;c++) s2v += out[c]*out[c];
        float* f = g_feats + (size_t)n*FEAT_ + h*SEG_;
        #pragma unroll
        for (int c=0;c<16;c++) f[168+p*16+c]=out[c];
        f[296+p*2+0]=sqrtf(s1v);
        f[296+p*2+1]=sqrtf(s2v);
    }
    if (tid < H_) {
        int h=tid;
        const float* oc = g_Ocat + ((size_t)h*N_+n)*VCP_;
        float aq0=oc[256], aq1=oc[257], aq2=oc[258], aq3=oc[259];
        float qc[4] = {qn[0], -qn[1], -qn[2], -qn[3]};
        float qr0 = qc[0]*aq0 - qc[1]*aq1 - qc[2]*aq2 - qc[3]*aq3;
        float qr1 = qc[0]*aq1 + qc[1]*aq0 + qc[2]*aq3 - qc[3]*aq2;
        float qr2 = qc[0]*aq2 - qc[1]*aq3 + qc[2]*aq0 + qc[3]*aq1;
        float qr3 = qc[0]*aq3 + qc[1]*aq2 - qc[2]*aq1 + qc[3]*aq0;
        float d[3] = {oc[260]-tr[0], oc[261]-tr[1], oc[262]-tr[2]};
        float trel[3];
        qrot(qc, d, trel);
        float* f = g_feats + (size_t)n*FEAT_ + h*SEG_ + 160;
        f[0]=qr0; f[1]=qr1; f[2]=qr2; f[3]=qr3;
        f[4]=trel[0]; f[5]=trel[1]; f[6]=trel[2]; f[7]=0.f;
    }
}

// ---------------- out init (bias) ----------------
__global__ void out_init_kernel(float* __restrict__ out, const float* __restrict__ b_out) {
    int idx = blockIdx.x*256 + threadIdx.x;
    if (idx < 512*384) out[idx] = b_out[idx % 384];
}

// ---------------- g_out ----------------
__global__ void gout_kernel(const float* __restrict__ W_geo, float* __restrict__ out) {
    int n = blockIdx.x, tid = threadIdx.x;  // 128
    int o = tid>>4, c = tid&15;
    float acc = 0.f;
    #pragma unroll
    for (int i2=0; i2<64; i2++) {
        acc += W_geo[o*64+i2] * g_feats[(size_t)n*FEAT_ + (i2>>3)*SEG_ + 168 + (i2&7)*16 + c];
    }
    out[(size_t)n*128 + o*16 + c] = acc;
}

// ---------------- launch ----------------
extern "C" void kernel_launch(void* const* d_in, const int* in_sizes, int n_in,
                              void* d_out, int out_size) {
    const float* s    = (const float*)d_in[0];
    const float* gin  = (const float*)d_in[1];
    const float* z    = (const float*)d_in[2];
    const float* T    = (const float*)d_in[3];
    const float* mask = (const float*)d_in[4];
    const float* W_q  = (const float*)d_in[5];
    const float* b_q  = (const float*)d_in[6];
    const float* W_kv = (const float*)d_in[7];
    const float* b_kv = (const float*)d_in[8];
    const float* W_qp = (const float*)d_in[9];
    const float* b_qp = (const float*)d_in[10];
    const float* W_kp = (const float*)d_in[11];
    const float* b_kp = (const float*)d_in[12];
    const float* W_vg = (const float*)d_in[13];
    const float* b_vg = (const float*)d_in[14];
    const float* W_mg = (const float*)d_in[15];
    const float* W_b  = (const float*)d_in[16];
    const float* b_b  = (const float*)d_in[17];
    const float* W_dz = (const float*)d_in[18];
    const float* b_dz = (const float*)d_in[19];
    const float* head_weights    = (const float*)d_in[20];
    const float* softmax_weights = (const float*)d_in[21];
    const float* W_out = (const float*)d_in[22];
    const float* b_out = (const float*)d_in[23];
    const float* W_geo = (const float*)d_in[24];
    float* out = (float*)d_out;

    float *pWcat, *pbcat, *pproj, *pfeats;
    cudaGetSymbolAddress((void**)&pWcat,  g_Wcat);
    cudaGetSymbolAddress((void**)&pbcat,  g_bcat);
    cudaGetSymbolAddress((void**)&pproj,  g_proj);
    cudaGetSymbolAddress((void**)&pfeats, g_feats);

    frames_kernel<<<2,256>>>(T, head_weights);
    pack_kernel<<<(384*PROJ_+255)/256,256>>>(W_q,W_kv,W_qp,W_kp,W_vg, b_q,b_kv,b_qp,b_kp,b_vg);
    zero_kernel<<<(H_*N_*VCP_+255)/256,256>>>();
    zfuse_kernel<<<4096,256>>>(z, W_b, W_dz, b_dz);

    // fused projections: [512,384] @ [384,3584]
    sgemm128<<<dim3(PROJ_/128, N_/128), 256>>>(s, pWcat, pbcat, pproj, PROJ_, 384);

    pts_pack_kernel<<<512,128>>>();
    vg_kernel<<<512,128>>>(gin, W_mg);

    logits_kernel<<<dim3(4,4,8), 256>>>(b_b, softmax_weights, mask);
    softmax_kernel<<<4096,256>>>();
    av_kernel<<<dim3(3,4,16), 256>>>();
    opair_kernel<<<512,256>>>();
    finalize_kernel<<<512,128>>>();

    out_init_kernel<<<768,256>>>(out, b_out);
    // W_out: [512,2496] @ [2496,384], split-K = 12 x 208
    sgemm_splitk<<<dim3(3,4,12), 256>>>(pfeats, W_out, out, 384, FEAT_, 208);
    gout_kernel<<<512,128>>>(W_geo, out + 512*384);
}